// round 7
// baseline (speedup 1.0000x reference)
#include <cuda_runtime.h>
#include <cuda_bf16.h>
#include <stdint.h>

#define B_ 512
#define T_ 32
#define D_ 512
#define M_ 1024
#define N_ (B_*T_)          // 16384

// ---------------- scratch ----------------
__device__ __align__(16) __nv_bfloat16 g_a_bf[N_*D_];
__device__ __align__(16) __nv_bfloat16 g_v_bf[N_*D_];
__device__ __align__(16) __nv_bfloat16 g_e_bf[M_*D_];
__device__ float g_an[N_];
__device__ float g_vn[N_];
__device__ float g_en[M_];
__device__ __align__(16) __nv_bfloat16 g_sd_a[N_*M_];
__device__ __align__(16) __nv_bfloat16 g_sd_v[N_*M_];
__device__ __align__(16) __nv_bfloat16 g_adj_a[N_*M_];
__device__ __align__(16) __nv_bfloat16 g_adj_v[N_*M_];
__device__ float g_L_a[N_];
__device__ float g_L_v[N_];
__device__ float g_rowsum[2*T_*B_];
__device__ float g_diag[2*T_*B_];
__device__ double g_part[64];

// ---------------- reduction helpers ----------------
__device__ __forceinline__ float warpRedSum(float v){
  #pragma unroll
  for (int o=16;o>0;o>>=1) v += __shfl_xor_sync(0xffffffffu, v, o);
  return v;
}
__device__ __forceinline__ float warpRedMin(float v){
  #pragma unroll
  for (int o=16;o>0;o>>=1) v = fminf(v, __shfl_xor_sync(0xffffffffu, v, o));
  return v;
}
__device__ float blockSum(float v){
  __shared__ float sm[32]; __shared__ float res;
  int lane = threadIdx.x & 31, w = threadIdx.x >> 5, nw = blockDim.x >> 5;
  v = warpRedSum(v);
  if (!lane) sm[w] = v;
  __syncthreads();
  if (w == 0){
    float t = (lane < nw) ? sm[lane] : 0.f;
    t = warpRedSum(t);
    if (!lane) res = t;
  }
  __syncthreads();
  return res;
}

__global__ void k_zero(float* rs){ rs[blockIdx.x*512 + threadIdx.x] = 0.f; }

// ---------------- merged convert + row sq-norm (warp per row, all 3 tensors) ----------------
__global__ void k_prep(const float* __restrict__ a, const float* __restrict__ v,
                       const float* __restrict__ e,
                       __nv_bfloat16* __restrict__ ab, __nv_bfloat16* __restrict__ vb,
                       __nv_bfloat16* __restrict__ eb,
                       float* __restrict__ an, float* __restrict__ vn,
                       float* __restrict__ en){
  int row = blockIdx.x*8 + (threadIdx.x >> 5);
  int lane = threadIdx.x & 31;
  const float* x; __nv_bfloat16* xb; float* nrm; int r;
  if (row < N_){ x=a; xb=ab; nrm=an; r=row; }
  else if (row < 2*N_){ x=v; xb=vb; nrm=vn; r=row-N_; }
  else { x=e; xb=eb; nrm=en; r=row-2*N_; }
  const float4* src = (const float4*)(x + (size_t)r * D_);
  uint2* dst = (uint2*)(xb + (size_t)r * D_);
  float s = 0.f;
  #pragma unroll
  for (int i=0;i<4;i++){
    float4 f = src[lane + 32*i];
    s += f.x*f.x + f.y*f.y + f.z*f.z + f.w*f.w;
    __nv_bfloat162 h0 = __floats2bfloat162_rn(f.x, f.y);
    __nv_bfloat162 h1 = __floats2bfloat162_rn(f.z, f.w);
    uint2 o; o.x = *(unsigned*)&h0; o.y = *(unsigned*)&h1;
    dst[lane + 32*i] = o;
  }
  s = warpRedSum(s);
  if (!lane) nrm[r] = s;
}

// ---------------- HMMA machinery ----------------
__device__ __forceinline__ void cpa16(uint32_t s, const void* g){
  asm volatile("cp.async.cg.shared.global [%0], [%1], 16;" :: "r"(s), "l"(g));
}
__device__ __forceinline__ void ldmx4(uint32_t* r, uint32_t a){
  asm volatile("ldmatrix.sync.aligned.m8n8.x4.shared.b16 {%0,%1,%2,%3}, [%4];"
    : "=r"(r[0]), "=r"(r[1]), "=r"(r[2]), "=r"(r[3]) : "r"(a));
}
__device__ __forceinline__ void mma_bf16(float* c, const uint32_t* a, uint32_t b0, uint32_t b1){
  asm volatile("mma.sync.aligned.m16n8k16.row.col.f32.bf16.bf16.f32 "
    "{%0,%1,%2,%3}, {%4,%5,%6,%7}, {%8,%9}, {%0,%1,%2,%3};"
    : "+f"(c[0]), "+f"(c[1]), "+f"(c[2]), "+f"(c[3])
    : "r"(a[0]), "r"(a[1]), "r"(a[2]), "r"(a[3]), "r"(b0), "r"(b1));
}

// CTA tile 128(M) x 256(N), BK=64 (128B rows). 256 threads, 8 warps (2M x 4N),
// warp tile 64x64. NBUF=4, single __syncthreads per K-chunk.
#define NBUF 4
#define ABYTES 16384
#define STG 49152
#define SMEM_DYN (NBUF*STG)   // 192KB

__device__ __forceinline__ void g_load(uint32_t sbase, int st, int ck,
                                       const char* Ab, const char* Bb,
                                       long ldab, long ldbb, int tid){
  uint32_t dA = sbase + (uint32_t)st * STG;
  uint32_t dB = dA + ABYTES;
  long koff = (long)ck * 128;
  #pragma unroll
  for (int i=0;i<4;i++){                 // A: 1024 x 16B
    int idx = tid + (i<<8); int r = idx >> 3, c = idx & 7;
    uint32_t off = (uint32_t)(r*128 + ((c ^ (r&7))<<4));
    cpa16(dA + off, Ab + (long)r*ldab + koff + c*16);
  }
  #pragma unroll
  for (int i=0;i<8;i++){                 // B: 2048 x 16B
    int idx = tid + (i<<8); int r = idx >> 3, c = idx & 7;
    uint32_t off = (uint32_t)(r*128 + ((c ^ (r&7))<<4));
    cpa16(dB + off, Bb + (long)r*ldbb + koff + c*16);
  }
  asm volatile("cp.async.commit_group;");
}

template<int KT>
__device__ __forceinline__ void g_main(uint32_t sbase, const char* Ab, const char* Bb,
                                       long ldab, long ldbb,
                                       float acc[4][8][4], int tid, int lane,
                                       int wm, int wn){
  g_load(sbase, 0, 0, Ab, Bb, ldab, ldbb, tid);
  g_load(sbase, 1, 1, Ab, Bb, ldab, ldbb, tid);
  g_load(sbase, 2, 2, Ab, Bb, ldab, ldbb, tid);
  #pragma unroll 1
  for (int kt = 0; kt < KT; ++kt){
    asm volatile("cp.async.wait_group 2;");
    __syncthreads();
    if (kt+3 < KT) g_load(sbase, (kt+3)&3, kt+3, Ab, Bb, ldab, ldbb, tid);
    else asm volatile("cp.async.commit_group;");
    uint32_t aB = sbase + (uint32_t)(kt&3) * STG;
    uint32_t bB = aB + ABYTES;
    #pragma unroll
    for (int ks=0; ks<4; ++ks){
      uint32_t af[4][4], bfr[4][4];
      #pragma unroll
      for (int mi=0; mi<4; ++mi){
        int row = wm + mi*16 + (lane & 15);
        int ch  = 2*ks + (lane >> 4);
        ldmx4(af[mi], aB + (uint32_t)(row*128 + ((ch ^ (row&7))<<4)));
      }
      #pragma unroll
      for (int p=0; p<4; ++p){
        int row = wn + p*16 + ((lane>>4)<<3) + (lane&7);
        int ch  = 2*ks + ((lane>>3)&1);
        ldmx4(bfr[p], bB + (uint32_t)(row*128 + ((ch ^ (row&7))<<4)));
      }
      #pragma unroll
      for (int mi=0; mi<4; ++mi)
        #pragma unroll
        for (int ni=0; ni<8; ++ni){
          const uint32_t* bp = bfr[ni>>1];
          uint32_t b0 = (ni&1) ? bp[2] : bp[0];
          uint32_t b1 = (ni&1) ? bp[3] : bp[1];
          mma_bf16(acc[mi][ni], af[mi], b0, b1);
        }
    }
  }
}

// ---------------- GEMM1: sd = bf16(sqrt(max(rn+cn-2*A.E^T,0))), both modalities ----------------
__global__ void __launch_bounds__(256, 1)
k_g1(const __nv_bfloat16* __restrict__ A0, const __nv_bfloat16* __restrict__ A1,
     const __nv_bfloat16* __restrict__ E,
     __nv_bfloat16* __restrict__ C0, __nv_bfloat16* __restrict__ C1,
     const float* __restrict__ rn0, const float* __restrict__ rn1,
     const float* __restrict__ cn)
{
  extern __shared__ char dsm[];
  uint32_t sbase = (uint32_t)__cvta_generic_to_shared(dsm);
  const int tid = threadIdx.x, lane = tid & 31, warp = tid >> 5;
  const int wm = (warp >> 2) * 64, wn = (warp & 3) * 64;
  const int z = blockIdx.z;
  const __nv_bfloat16* A = z ? A1 : A0;
  const float* rn = z ? rn1 : rn0;
  __nv_bfloat16* C = z ? C1 : C0;

  const char* Ab = (const char*)A + (long)blockIdx.y * 128 * 1024;
  const char* Bb = (const char*)E + (long)blockIdx.x * 256 * 1024;

  float acc[4][8][4];
  #pragma unroll
  for (int a=0;a<4;a++)
    #pragma unroll
    for (int b=0;b<8;b++)
      #pragma unroll
      for (int c=0;c<4;c++) acc[a][b][c]=0.f;

  g_main<8>(sbase, Ab, Bb, 1024, 1024, acc, tid, lane, wm, wn);

  const int tr = lane >> 2, tc = (lane & 3) * 2;
  #pragma unroll
  for (int mi=0; mi<4; ++mi){
    int r0 = blockIdx.y*128 + wm + mi*16 + tr;
    float rn0v = rn[r0], rn1v = rn[r0+8];
    #pragma unroll
    for (int ni=0; ni<8; ++ni){
      int col = blockIdx.x*256 + wn + ni*8 + tc;
      float c0 = cn[col], c1 = cn[col+1];
      float* a = acc[mi][ni];
      __nv_bfloat162 o0 = __floats2bfloat162_rn(
          sqrtf(fmaxf(fmaf(-2.f, a[0], rn0v + c0), 0.f)),
          sqrtf(fmaxf(fmaf(-2.f, a[1], rn0v + c1), 0.f)));
      __nv_bfloat162 o1 = __floats2bfloat162_rn(
          sqrtf(fmaxf(fmaf(-2.f, a[2], rn1v + c0), 0.f)),
          sqrtf(fmaxf(fmaf(-2.f, a[3], rn1v + c1), 0.f)));
      *(__nv_bfloat162*)&C[(long)r0*M_ + col] = o0;
      *(__nv_bfloat162*)&C[(long)(r0+8)*M_ + col] = o1;
    }
  }
}

// ---------------- softmax (warp per row): adj = softmax(-2 sd), L = lse(-sd) ----------------
// 256 threads = 8 warps = 8 rows/block; each lane holds 32 of the 1024 row values.
__global__ void __launch_bounds__(256)
k_softmax2(const __nv_bfloat16* __restrict__ sda,
           const __nv_bfloat16* __restrict__ sdv,
           __nv_bfloat16* __restrict__ adja,
           __nv_bfloat16* __restrict__ adjv,
           float* __restrict__ La, float* __restrict__ Lv){
  int rowg = blockIdx.x*8 + (threadIdx.x >> 5);
  int lane = threadIdx.x & 31;
  int which = rowg >> 14;
  int row = rowg & (N_-1);
  const __nv_bfloat16* sd = which ? sdv : sda;
  __nv_bfloat16* adj = which ? adjv : adja;
  float* L = which ? Lv : La;
  size_t base = (size_t)row * M_;
  const uint2* src = (const uint2*)(sd + base);   // 256 uint2 per row
  uint2* dst = (uint2*)(adj + base);

  float v[32];
  float vmin = 3.4e38f;
  #pragma unroll
  for (int j=0;j<8;j++){
    uint2 pk = src[lane + 32*j];
    __nv_bfloat162 p0 = *(__nv_bfloat162*)&pk.x;
    __nv_bfloat162 p1 = *(__nv_bfloat162*)&pk.y;
    float f0 = __low2float(p0), f1 = __high2float(p0);
    float f2 = __low2float(p1), f3 = __high2float(p1);
    v[4*j]=f0; v[4*j+1]=f1; v[4*j+2]=f2; v[4*j+3]=f3;
    vmin = fminf(vmin, fminf(fminf(f0,f1), fminf(f2,f3)));
  }
  float rmin = warpRedMin(vmin);
  float s1 = 0.f, s2 = 0.f;
  #pragma unroll
  for (int k=0;k<32;k++){
    float e = __expf(rmin - v[k]);
    v[k] = e;
    s1 += e; s2 += e*e;
  }
  s1 = warpRedSum(s1);
  s2 = warpRedSum(s2);
  float i2 = 1.0f/s2;
  #pragma unroll
  for (int j=0;j<8;j++){
    float e0=v[4*j], e1=v[4*j+1], e2=v[4*j+2], e3=v[4*j+3];
    __nv_bfloat162 a0 = __floats2bfloat162_rn(e0*e0*i2, e1*e1*i2);
    __nv_bfloat162 a1 = __floats2bfloat162_rn(e2*e2*i2, e3*e3*i2);
    uint2 o; o.x = *(unsigned*)&a0; o.y = *(unsigned*)&a1;
    dst[lane + 32*j] = o;
  }
  if (!lane) L[row] = logf(s1) - rmin;
}

// ---------------- GEMM2 + fused loss epilogue ----------------
__global__ void __launch_bounds__(256, 1)
k_g2(const __nv_bfloat16* __restrict__ adjA, const __nv_bfloat16* __restrict__ adjV,
     const __nv_bfloat16* __restrict__ sdA,  const __nv_bfloat16* __restrict__ sdV,
     const float* __restrict__ La, const float* __restrict__ Lv,
     float* __restrict__ rowsum, float* __restrict__ diag)
{
  extern __shared__ char dsm[];
  uint32_t sbase = (uint32_t)__cvta_generic_to_shared(dsm);
  const int tid = threadIdx.x, lane = tid & 31, warp = tid >> 5;
  const int wm = (warp >> 2) * 64, wn = (warp & 3) * 64;
  const int pair = blockIdx.z >> 5, t = blockIdx.z & 31;
  const __nv_bfloat16* A = pair ? adjV : adjA;
  const __nv_bfloat16* Bm = pair ? sdA : sdV;
  const float* L = pair ? La : Lv;

  const char* Ab = (const char*)A + (long)t*2048 + (long)blockIdx.y * 128 * 65536;
  const char* Bb = (const char*)Bm + (long)t*2048 + (long)blockIdx.x * 256 * 65536;

  float acc[4][8][4];
  #pragma unroll
  for (int a=0;a<4;a++)
    #pragma unroll
    for (int b=0;b<8;b++)
      #pragma unroll
      for (int c=0;c<4;c++) acc[a][b][c]=0.f;

  g_main<16>(sbase, Ab, Bb, 65536, 65536, acc, tid, lane, wm, wn);

  const int tr = lane >> 2, tc = (lane & 3) * 2;
  const int batch = pair*T_ + t;
  float* dout = diag + (long)batch * B_;
  float rp[8];
  #pragma unroll
  for (int i=0;i<8;i++) rp[i]=0.f;
  #pragma unroll
  for (int mi=0; mi<4; ++mi){
    int rloc = wm + mi*16 + tr;
    int gi0 = blockIdx.y*128 + rloc;
    #pragma unroll
    for (int ni=0; ni<8; ++ni){
      int gj = blockIdx.x*256 + wn + ni*8 + tc;
      float L0 = L[(long)gj*T_ + t];
      float L1 = L[(long)(gj+1)*T_ + t];
      float* a = acc[mi][ni];
      float p00 = __expf(-a[0]-L0), p01 = __expf(-a[1]-L1);
      float p10 = __expf(-a[2]-L0), p11 = __expf(-a[3]-L1);
      rp[mi*2]   += p00 + p01;
      rp[mi*2+1] += p10 + p11;
      if (gj   == gi0)   dout[gi0]   = p00;
      if (gj+1 == gi0)   dout[gi0]   = p01;
      if (gj   == gi0+8) dout[gi0+8] = p10;
      if (gj+1 == gi0+8) dout[gi0+8] = p11;
    }
  }
  #pragma unroll
  for (int i=0;i<8;i++){
    rp[i] += __shfl_xor_sync(0xffffffffu, rp[i], 1);
    rp[i] += __shfl_xor_sync(0xffffffffu, rp[i], 2);
  }
  __syncthreads();
  float* part = (float*)dsm;               // [128][4]
  int ng = warp & 3;
  if ((lane & 3) == 0){
    #pragma unroll
    for (int mi=0; mi<4; ++mi){
      int r = wm + mi*16 + tr;
      part[r*4 + ng]     = rp[mi*2];
      part[(r+8)*4 + ng] = rp[mi*2+1];
    }
  }
  __syncthreads();
  if (tid < 128){
    float s = part[tid*4] + part[tid*4+1] + part[tid*4+2] + part[tid*4+3];
    atomicAdd(&rowsum[(long)batch*B_ + blockIdx.y*128 + tid], s);
  }
}

// ---------------- loss partials and final mean ----------------
__global__ void k_loss2(const float* __restrict__ rs, const float* __restrict__ dg,
                        double* __restrict__ part){
  long base = (long)blockIdx.x * B_;
  float term = 0.f;
  #pragma unroll
  for (int h=0; h<2; ++h){
    long i = base + threadIdx.x + h*256;
    term += logf(rs[i]) - logf(dg[i]);
  }
  float s = blockSum(term);
  if (threadIdx.x == 0) part[blockIdx.x] = (double)s;
}
__global__ void k_final(const double* __restrict__ part, float* __restrict__ out){
  double s = (threadIdx.x < 64) ? part[threadIdx.x] : 0.0;
  #pragma unroll
  for (int o=16;o>0;o>>=1) s += __shfl_xor_sync(0xffffffffu, s, o);
  __shared__ double sm[2];
  if ((threadIdx.x & 31) == 0) sm[threadIdx.x>>5] = s;
  __syncthreads();
  if (threadIdx.x == 0) out[0] = (float)((sm[0]+sm[1]) / 32768.0);
}

// ---------------- launch ----------------
extern "C" void kernel_launch(void* const* d_in, const int* in_sizes, int n_in,
                              void* d_out, int out_size)
{
  const float* a = (const float*)d_in[0];
  const float* v = (const float*)d_in[1];
  const float* e = (const float*)d_in[2];
  float* out = (float*)d_out;

  __nv_bfloat16 *pa, *pv, *pe, *psa, *psv, *paa, *pav;
  float *pan, *pvn, *pen, *pLa, *pLv, *prs, *pdg;
  double *ppt;
  cudaGetSymbolAddress((void**)&pa,  g_a_bf);
  cudaGetSymbolAddress((void**)&pv,  g_v_bf);
  cudaGetSymbolAddress((void**)&pe,  g_e_bf);
  cudaGetSymbolAddress((void**)&pan, g_an);
  cudaGetSymbolAddress((void**)&pvn, g_vn);
  cudaGetSymbolAddress((void**)&pen, g_en);
  cudaGetSymbolAddress((void**)&psa, g_sd_a);
  cudaGetSymbolAddress((void**)&psv, g_sd_v);
  cudaGetSymbolAddress((void**)&paa, g_adj_a);
  cudaGetSymbolAddress((void**)&pav, g_adj_v);
  cudaGetSymbolAddress((void**)&pLa, g_L_a);
  cudaGetSymbolAddress((void**)&pLv, g_L_v);
  cudaGetSymbolAddress((void**)&prs, g_rowsum);
  cudaGetSymbolAddress((void**)&pdg, g_diag);
  cudaGetSymbolAddress((void**)&ppt, g_part);

  cudaFuncSetAttribute(k_g1, cudaFuncAttributeMaxDynamicSharedMemorySize, SMEM_DYN);
  cudaFuncSetAttribute(k_g2, cudaFuncAttributeMaxDynamicSharedMemorySize, SMEM_DYN);

  k_zero<<<64, 512>>>(prs);
  k_prep<<<(2*N_+M_)/8, 256>>>(a, v, e, pa, pv, pe, pan, pvn, pen);

  dim3 g1(M_/256, N_/128, 2);
  k_g1<<<g1, 256, SMEM_DYN>>>(pa, pv, pe, psa, psv, pan, pvn, pen);

  k_softmax2<<<2*N_/8, 256>>>(psa, psv, paa, pav, pLa, pLv);

  dim3 g2(B_/256, B_/128, 64);
  k_g2<<<g2, 256, SMEM_DYN>>>(paa, pav, psa, psv, pLa, pLv, prs, pdg);

  k_loss2<<<64, 256>>>(prs, pdg, ppt);
  k_final<<<1, 64>>>(ppt, out);
}

// round 8
// speedup vs baseline: 1.6591x; 1.6591x over previous
#include <cuda_runtime.h>
#include <cuda_bf16.h>
#include <stdint.h>

#define B_ 512
#define T_ 32
#define D_ 512
#define M_ 1024
#define N_ (B_*T_)          // 16384

// ---------------- scratch ----------------
__device__ __align__(16) __nv_bfloat16 g_a_bf[N_*D_];
__device__ __align__(16) __nv_bfloat16 g_v_bf[N_*D_];
__device__ __align__(16) __nv_bfloat16 g_e_bf[M_*D_];
__device__ float g_an[N_];
__device__ float g_vn[N_];
__device__ float g_en[M_];
__device__ __align__(16) __nv_bfloat16 g_sd_a[N_*M_];
__device__ __align__(16) __nv_bfloat16 g_sd_v[N_*M_];
__device__ __align__(16) __nv_bfloat16 g_adj_a[N_*M_];
__device__ __align__(16) __nv_bfloat16 g_adj_v[N_*M_];
__device__ float g_L_a[N_];
__device__ float g_L_v[N_];
__device__ float g_rowsum[2*T_*B_];
__device__ float g_diag[2*T_*B_];
__device__ double g_part[64];

// ---------------- reduction helpers ----------------
__device__ __forceinline__ float warpRedSum(float v){
  #pragma unroll
  for (int o=16;o>0;o>>=1) v += __shfl_xor_sync(0xffffffffu, v, o);
  return v;
}
__device__ __forceinline__ float warpRedMin(float v){
  #pragma unroll
  for (int o=16;o>0;o>>=1) v = fminf(v, __shfl_xor_sync(0xffffffffu, v, o));
  return v;
}
__device__ float blockSum(float v){
  __shared__ float sm[32]; __shared__ float res;
  int lane = threadIdx.x & 31, w = threadIdx.x >> 5, nw = blockDim.x >> 5;
  v = warpRedSum(v);
  if (!lane) sm[w] = v;
  __syncthreads();
  if (w == 0){
    float t = (lane < nw) ? sm[lane] : 0.f;
    t = warpRedSum(t);
    if (!lane) res = t;
  }
  __syncthreads();
  return res;
}

__global__ void k_zero(float* rs){ rs[blockIdx.x*512 + threadIdx.x] = 0.f; }

// ---------------- merged convert + row sq-norm (warp per row, all 3 tensors) ----------------
__global__ void k_prep(const float* __restrict__ a, const float* __restrict__ v,
                       const float* __restrict__ e,
                       __nv_bfloat16* __restrict__ ab, __nv_bfloat16* __restrict__ vb,
                       __nv_bfloat16* __restrict__ eb,
                       float* __restrict__ an, float* __restrict__ vn,
                       float* __restrict__ en){
  int row = blockIdx.x*8 + (threadIdx.x >> 5);
  int lane = threadIdx.x & 31;
  const float* x; __nv_bfloat16* xb; float* nrm; int r;
  if (row < N_){ x=a; xb=ab; nrm=an; r=row; }
  else if (row < 2*N_){ x=v; xb=vb; nrm=vn; r=row-N_; }
  else { x=e; xb=eb; nrm=en; r=row-2*N_; }
  const float4* src = (const float4*)(x + (size_t)r * D_);
  uint2* dst = (uint2*)(xb + (size_t)r * D_);
  float s = 0.f;
  #pragma unroll
  for (int i=0;i<4;i++){
    float4 f = src[lane + 32*i];
    s += f.x*f.x + f.y*f.y + f.z*f.z + f.w*f.w;
    __nv_bfloat162 h0 = __floats2bfloat162_rn(f.x, f.y);
    __nv_bfloat162 h1 = __floats2bfloat162_rn(f.z, f.w);
    uint2 o; o.x = *(unsigned*)&h0; o.y = *(unsigned*)&h1;
    dst[lane + 32*i] = o;
  }
  s = warpRedSum(s);
  if (!lane) nrm[r] = s;
}

// ---------------- HMMA machinery ----------------
__device__ __forceinline__ void cpa16(uint32_t s, const void* g){
  asm volatile("cp.async.cg.shared.global [%0], [%1], 16;" :: "r"(s), "l"(g));
}
__device__ __forceinline__ void ldmx4(uint32_t* r, uint32_t a){
  asm volatile("ldmatrix.sync.aligned.m8n8.x4.shared.b16 {%0,%1,%2,%3}, [%4];"
    : "=r"(r[0]), "=r"(r[1]), "=r"(r[2]), "=r"(r[3]) : "r"(a));
}
__device__ __forceinline__ void mma_bf16(float* c, const uint32_t* a, uint32_t b0, uint32_t b1){
  asm volatile("mma.sync.aligned.m16n8k16.row.col.f32.bf16.bf16.f32 "
    "{%0,%1,%2,%3}, {%4,%5,%6,%7}, {%8,%9}, {%0,%1,%2,%3};"
    : "+f"(c[0]), "+f"(c[1]), "+f"(c[2]), "+f"(c[3])
    : "r"(a[0]), "r"(a[1]), "r"(a[2]), "r"(a[3]), "r"(b0), "r"(b1));
}

// CTA tile 128(M) x 128(N), BK=64 (128B rows). 128 threads, 4 warps (2M x 2N),
// warp tile 64x64. NBUF=3 (96KB) -> 2 CTAs/SM. Single __syncthreads per K-chunk.
#define NBUF 3
#define ABYTES 16384
#define STG 32768
#define SMEM_DYN (NBUF*STG)   // 96KB

__device__ __forceinline__ void g_load(uint32_t sbase, int st, int ck,
                                       const char* Ab, const char* Bb,
                                       long ldab, long ldbb, int tid){
  uint32_t dA = sbase + (uint32_t)st * STG;
  uint32_t dB = dA + ABYTES;
  long koff = (long)ck * 128;
  #pragma unroll
  for (int i=0;i<8;i++){                 // A: 1024 x 16B chunks / 128 threads
    int idx = tid + (i<<7); int r = idx >> 3, c = idx & 7;
    uint32_t off = (uint32_t)(r*128 + ((c ^ (r&7))<<4));
    cpa16(dA + off, Ab + (long)r*ldab + koff + c*16);
  }
  #pragma unroll
  for (int i=0;i<8;i++){                 // B: 1024 x 16B chunks
    int idx = tid + (i<<7); int r = idx >> 3, c = idx & 7;
    uint32_t off = (uint32_t)(r*128 + ((c ^ (r&7))<<4));
    cpa16(dB + off, Bb + (long)r*ldbb + koff + c*16);
  }
  asm volatile("cp.async.commit_group;");
}

template<int KT>
__device__ __forceinline__ void g_main(uint32_t sbase, const char* Ab, const char* Bb,
                                       long ldab, long ldbb,
                                       float acc[4][8][4], int tid, int lane,
                                       int wm, int wn){
  g_load(sbase, 0, 0, Ab, Bb, ldab, ldbb, tid);
  g_load(sbase, 1, 1, Ab, Bb, ldab, ldbb, tid);
  #pragma unroll 1
  for (int kt = 0; kt < KT; ++kt){
    asm volatile("cp.async.wait_group 1;");
    __syncthreads();
    // buffer (kt+2)%3 == (kt-1)%3 for kt>=1: reads finished in iter kt-1, proven by sync above
    if (kt+2 < KT){
      int st = (kt+2)%3;
      g_load(sbase, st, kt+2, Ab, Bb, ldab, ldbb, tid);
    } else {
      asm volatile("cp.async.commit_group;");
    }
    uint32_t aB = sbase + (uint32_t)(kt%3) * STG;
    uint32_t bB = aB + ABYTES;
    #pragma unroll
    for (int ks=0; ks<4; ++ks){
      uint32_t af[4][4], bfr[4][4];
      #pragma unroll
      for (int mi=0; mi<4; ++mi){
        int row = wm + mi*16 + (lane & 15);
        int ch  = 2*ks + (lane >> 4);
        ldmx4(af[mi], aB + (uint32_t)(row*128 + ((ch ^ (row&7))<<4)));
      }
      #pragma unroll
      for (int p=0; p<4; ++p){
        int row = wn + p*16 + ((lane>>4)<<3) + (lane&7);
        int ch  = 2*ks + ((lane>>3)&1);
        ldmx4(bfr[p], bB + (uint32_t)(row*128 + ((ch ^ (row&7))<<4)));
      }
      #pragma unroll
      for (int mi=0; mi<4; ++mi)
        #pragma unroll
        for (int ni=0; ni<8; ++ni){
          const uint32_t* bp = bfr[ni>>1];
          uint32_t b0 = (ni&1) ? bp[2] : bp[0];
          uint32_t b1 = (ni&1) ? bp[3] : bp[1];
          mma_bf16(acc[mi][ni], af[mi], b0, b1);
        }
    }
  }
}

// ---------------- GEMM1: sd = bf16(sqrt(max(rn+cn-2*A.E^T,0))), both modalities ----------------
__global__ void __launch_bounds__(128, 2)
k_g1(const __nv_bfloat16* __restrict__ A0, const __nv_bfloat16* __restrict__ A1,
     const __nv_bfloat16* __restrict__ E,
     __nv_bfloat16* __restrict__ C0, __nv_bfloat16* __restrict__ C1,
     const float* __restrict__ rn0, const float* __restrict__ rn1,
     const float* __restrict__ cn)
{
  extern __shared__ char dsm[];
  uint32_t sbase = (uint32_t)__cvta_generic_to_shared(dsm);
  const int tid = threadIdx.x, lane = tid & 31, warp = tid >> 5;
  const int wm = (warp & 1) * 64, wn = (warp >> 1) * 64;
  const int z = blockIdx.z;
  const __nv_bfloat16* A = z ? A1 : A0;
  const float* rn = z ? rn1 : rn0;
  __nv_bfloat16* C = z ? C1 : C0;

  const char* Ab = (const char*)A + (long)blockIdx.y * 128 * 1024;
  const char* Bb = (const char*)E + (long)blockIdx.x * 128 * 1024;

  float acc[4][8][4];
  #pragma unroll
  for (int a=0;a<4;a++)
    #pragma unroll
    for (int b=0;b<8;b++)
      #pragma unroll
      for (int c=0;c<4;c++) acc[a][b][c]=0.f;

  g_main<8>(sbase, Ab, Bb, 1024, 1024, acc, tid, lane, wm, wn);

  const int tr = lane >> 2, tc = (lane & 3) * 2;
  #pragma unroll
  for (int mi=0; mi<4; ++mi){
    int r0 = blockIdx.y*128 + wm + mi*16 + tr;
    float rn0v = rn[r0], rn1v = rn[r0+8];
    #pragma unroll
    for (int ni=0; ni<8; ++ni){
      int col = blockIdx.x*128 + wn + ni*8 + tc;
      float c0 = cn[col], c1 = cn[col+1];
      float* a = acc[mi][ni];
      __nv_bfloat162 o0 = __floats2bfloat162_rn(
          sqrtf(fmaxf(fmaf(-2.f, a[0], rn0v + c0), 0.f)),
          sqrtf(fmaxf(fmaf(-2.f, a[1], rn0v + c1), 0.f)));
      __nv_bfloat162 o1 = __floats2bfloat162_rn(
          sqrtf(fmaxf(fmaf(-2.f, a[2], rn1v + c0), 0.f)),
          sqrtf(fmaxf(fmaf(-2.f, a[3], rn1v + c1), 0.f)));
      *(__nv_bfloat162*)&C[(long)r0*M_ + col] = o0;
      *(__nv_bfloat162*)&C[(long)(r0+8)*M_ + col] = o1;
    }
  }
}

// ---------------- softmax (warp per row): adj = softmax(-2 sd), L = lse(-sd) ----------------
__global__ void __launch_bounds__(256)
k_softmax2(const __nv_bfloat16* __restrict__ sda,
           const __nv_bfloat16* __restrict__ sdv,
           __nv_bfloat16* __restrict__ adja,
           __nv_bfloat16* __restrict__ adjv,
           float* __restrict__ La, float* __restrict__ Lv){
  int rowg = blockIdx.x*8 + (threadIdx.x >> 5);
  int lane = threadIdx.x & 31;
  int which = rowg >> 14;
  int row = rowg & (N_-1);
  const __nv_bfloat16* sd = which ? sdv : sda;
  __nv_bfloat16* adj = which ? adjv : adja;
  float* L = which ? Lv : La;
  size_t base = (size_t)row * M_;
  const uint2* src = (const uint2*)(sd + base);
  uint2* dst = (uint2*)(adj + base);

  float v[32];
  float vmin = 3.4e38f;
  #pragma unroll
  for (int j=0;j<8;j++){
    uint2 pk = src[lane + 32*j];
    __nv_bfloat162 p0 = *(__nv_bfloat162*)&pk.x;
    __nv_bfloat162 p1 = *(__nv_bfloat162*)&pk.y;
    float f0 = __low2float(p0), f1 = __high2float(p0);
    float f2 = __low2float(p1), f3 = __high2float(p1);
    v[4*j]=f0; v[4*j+1]=f1; v[4*j+2]=f2; v[4*j+3]=f3;
    vmin = fminf(vmin, fminf(fminf(f0,f1), fminf(f2,f3)));
  }
  float rmin = warpRedMin(vmin);
  float s1 = 0.f, s2 = 0.f;
  #pragma unroll
  for (int k=0;k<32;k++){
    float e = __expf(rmin - v[k]);
    v[k] = e;
    s1 += e; s2 += e*e;
  }
  s1 = warpRedSum(s1);
  s2 = warpRedSum(s2);
  float i2 = 1.0f/s2;
  #pragma unroll
  for (int j=0;j<8;j++){
    float e0=v[4*j], e1=v[4*j+1], e2=v[4*j+2], e3=v[4*j+3];
    __nv_bfloat162 a0 = __floats2bfloat162_rn(e0*e0*i2, e1*e1*i2);
    __nv_bfloat162 a1 = __floats2bfloat162_rn(e2*e2*i2, e3*e3*i2);
    uint2 o; o.x = *(unsigned*)&a0; o.y = *(unsigned*)&a1;
    dst[lane + 32*j] = o;
  }
  if (!lane) L[row] = logf(s1) - rmin;
}

// ---------------- GEMM2 + fused loss epilogue ----------------
__global__ void __launch_bounds__(128, 2)
k_g2(const __nv_bfloat16* __restrict__ adjA, const __nv_bfloat16* __restrict__ adjV,
     const __nv_bfloat16* __restrict__ sdA,  const __nv_bfloat16* __restrict__ sdV,
     const float* __restrict__ La, const float* __restrict__ Lv,
     float* __restrict__ rowsum, float* __restrict__ diag)
{
  extern __shared__ char dsm[];
  uint32_t sbase = (uint32_t)__cvta_generic_to_shared(dsm);
  const int tid = threadIdx.x, lane = tid & 31, warp = tid >> 5;
  const int wm = (warp & 1) * 64, wn = (warp >> 1) * 64;
  const int pair = blockIdx.z >> 5, t = blockIdx.z & 31;
  const __nv_bfloat16* A = pair ? adjV : adjA;
  const __nv_bfloat16* Bm = pair ? sdA : sdV;
  const float* L = pair ? La : Lv;

  const char* Ab = (const char*)A + (long)t*2048 + (long)blockIdx.y * 128 * 65536;
  const char* Bb = (const char*)Bm + (long)t*2048 + (long)blockIdx.x * 128 * 65536;

  float acc[4][8][4];
  #pragma unroll
  for (int a=0;a<4;a++)
    #pragma unroll
    for (int b=0;b<8;b++)
      #pragma unroll
      for (int c=0;c<4;c++) acc[a][b][c]=0.f;

  g_main<16>(sbase, Ab, Bb, 65536, 65536, acc, tid, lane, wm, wn);

  const int tr = lane >> 2, tc = (lane & 3) * 2;
  const int batch = pair*T_ + t;
  float* dout = diag + (long)batch * B_;
  float rp[8];
  #pragma unroll
  for (int i=0;i<8;i++) rp[i]=0.f;
  #pragma unroll
  for (int mi=0; mi<4; ++mi){
    int gi0 = blockIdx.y*128 + wm + mi*16 + tr;
    #pragma unroll
    for (int ni=0; ni<8; ++ni){
      int gj = blockIdx.x*128 + wn + ni*8 + tc;
      float L0 = L[(long)gj*T_ + t];
      float L1 = L[(long)(gj+1)*T_ + t];
      float* a = acc[mi][ni];
      float p00 = __expf(-a[0]-L0), p01 = __expf(-a[1]-L1);
      float p10 = __expf(-a[2]-L0), p11 = __expf(-a[3]-L1);
      rp[mi*2]   += p00 + p01;
      rp[mi*2+1] += p10 + p11;
      if (gj   == gi0)   dout[gi0]   = p00;
      if (gj+1 == gi0)   dout[gi0]   = p01;
      if (gj   == gi0+8) dout[gi0+8] = p10;
      if (gj+1 == gi0+8) dout[gi0+8] = p11;
    }
  }
  #pragma unroll
  for (int i=0;i<8;i++){
    rp[i] += __shfl_xor_sync(0xffffffffu, rp[i], 1);
    rp[i] += __shfl_xor_sync(0xffffffffu, rp[i], 2);
  }
  __syncthreads();
  float* part = (float*)dsm;               // [128][2]
  int ng = warp >> 1;                      // N-half index
  if ((lane & 3) == 0){
    #pragma unroll
    for (int mi=0; mi<4; ++mi){
      int r = wm + mi*16 + tr;
      part[r*2 + ng]     = rp[mi*2];
      part[(r+8)*2 + ng] = rp[mi*2+1];
    }
  }
  __syncthreads();
  {
    float s = part[tid*2] + part[tid*2+1];
    atomicAdd(&rowsum[(long)batch*B_ + blockIdx.y*128 + tid], s);
  }
}

// ---------------- loss partials and final mean ----------------
__global__ void k_loss2(const float* __restrict__ rs, const float* __restrict__ dg,
                        double* __restrict__ part){
  long base = (long)blockIdx.x * B_;
  float term = 0.f;
  #pragma unroll
  for (int h=0; h<2; ++h){
    long i = base + threadIdx.x + h*256;
    term += logf(rs[i]) - logf(dg[i]);
  }
  float s = blockSum(term);
  if (threadIdx.x == 0) part[blockIdx.x] = (double)s;
}
__global__ void k_final(const double* __restrict__ part, float* __restrict__ out){
  double s = (threadIdx.x < 64) ? part[threadIdx.x] : 0.0;
  #pragma unroll
  for (int o=16;o>0;o>>=1) s += __shfl_xor_sync(0xffffffffu, s, o);
  __shared__ double sm[2];
  if ((threadIdx.x & 31) == 0) sm[threadIdx.x>>5] = s;
  __syncthreads();
  if (threadIdx.x == 0) out[0] = (float)((sm[0]+sm[1]) / 32768.0);
}

// ---------------- launch ----------------
extern "C" void kernel_launch(void* const* d_in, const int* in_sizes, int n_in,
                              void* d_out, int out_size)
{
  const float* a = (const float*)d_in[0];
  const float* v = (const float*)d_in[1];
  const float* e = (const float*)d_in[2];
  float* out = (float*)d_out;

  __nv_bfloat16 *pa, *pv, *pe, *psa, *psv, *paa, *pav;
  float *pan, *pvn, *pen, *pLa, *pLv, *prs, *pdg;
  double *ppt;
  cudaGetSymbolAddress((void**)&pa,  g_a_bf);
  cudaGetSymbolAddress((void**)&pv,  g_v_bf);
  cudaGetSymbolAddress((void**)&pe,  g_e_bf);
  cudaGetSymbolAddress((void**)&pan, g_an);
  cudaGetSymbolAddress((void**)&pvn, g_vn);
  cudaGetSymbolAddress((void**)&pen, g_en);
  cudaGetSymbolAddress((void**)&psa, g_sd_a);
  cudaGetSymbolAddress((void**)&psv, g_sd_v);
  cudaGetSymbolAddress((void**)&paa, g_adj_a);
  cudaGetSymbolAddress((void**)&pav, g_adj_v);
  cudaGetSymbolAddress((void**)&pLa, g_L_a);
  cudaGetSymbolAddress((void**)&pLv, g_L_v);
  cudaGetSymbolAddress((void**)&prs, g_rowsum);
  cudaGetSymbolAddress((void**)&pdg, g_diag);
  cudaGetSymbolAddress((void**)&ppt, g_part);

  cudaFuncSetAttribute(k_g1, cudaFuncAttributeMaxDynamicSharedMemorySize, SMEM_DYN);
  cudaFuncSetAttribute(k_g2, cudaFuncAttributeMaxDynamicSharedMemorySize, SMEM_DYN);

  k_zero<<<64, 512>>>(prs);
  k_prep<<<(2*N_+M_)/8, 256>>>(a, v, e, pa, pv, pe, pan, pvn, pen);

  dim3 g1(M_/128, N_/128, 2);
  k_g1<<<g1, 128, SMEM_DYN>>>(pa, pv, pe, psa, psv, pan, pvn, pen);

  k_softmax2<<<2*N_/8, 256>>>(psa, psv, paa, pav, pLa, pLv);

  dim3 g2(B_/128, B_/128, 64);
  k_g2<<<g2, 128, SMEM_DYN>>>(paa, pav, psa, psv, pLa, pLv, prs, pdg);

  k_loss2<<<64, 256>>>(prs, pdg, ppt);
  k_final<<<1, 64>>>(ppt, out);
}

// round 9
// speedup vs baseline: 1.6768x; 1.0106x over previous
#include <cuda_runtime.h>
#include <cuda_bf16.h>
#include <stdint.h>

#define B_ 512
#define T_ 32
#define D_ 512
#define M_ 1024
#define N_ (B_*T_)          // 16384

// ---------------- scratch ----------------
__device__ __align__(16) __nv_bfloat16 g_a_bf[N_*D_];
__device__ __align__(16) __nv_bfloat16 g_v_bf[N_*D_];
__device__ __align__(16) __nv_bfloat16 g_e_bf[M_*D_];
__device__ float g_an[N_];
__device__ float g_vn[N_];
__device__ float g_en[M_];
__device__ __align__(16) __nv_bfloat16 g_sd_a[N_*M_];
__device__ __align__(16) __nv_bfloat16 g_sd_v[N_*M_];
__device__ __align__(16) __nv_bfloat16 g_adj_a[N_*M_];
__device__ __align__(16) __nv_bfloat16 g_adj_v[N_*M_];
__device__ float g_L_a[N_];
__device__ float g_L_v[N_];
__device__ float g_rowsum[2*T_*B_];
__device__ float g_diag[2*T_*B_];
__device__ double g_part[64];

// ---------------- reduction helpers ----------------
__device__ __forceinline__ float warpRedSum(float v){
  #pragma unroll
  for (int o=16;o>0;o>>=1) v += __shfl_xor_sync(0xffffffffu, v, o);
  return v;
}
__device__ __forceinline__ float warpRedMin(float v){
  #pragma unroll
  for (int o=16;o>0;o>>=1) v = fminf(v, __shfl_xor_sync(0xffffffffu, v, o));
  return v;
}
__device__ float blockSum(float v){
  __shared__ float sm[32]; __shared__ float res;
  int lane = threadIdx.x & 31, w = threadIdx.x >> 5, nw = blockDim.x >> 5;
  v = warpRedSum(v);
  if (!lane) sm[w] = v;
  __syncthreads();
  if (w == 0){
    float t = (lane < nw) ? sm[lane] : 0.f;
    t = warpRedSum(t);
    if (!lane) res = t;
  }
  __syncthreads();
  return res;
}

__global__ void k_zero(float* rs){ rs[blockIdx.x*512 + threadIdx.x] = 0.f; }

// ---------------- merged convert + row sq-norm (warp per row, all 3 tensors) ----------------
__global__ void k_prep(const float* __restrict__ a, const float* __restrict__ v,
                       const float* __restrict__ e,
                       __nv_bfloat16* __restrict__ ab, __nv_bfloat16* __restrict__ vb,
                       __nv_bfloat16* __restrict__ eb,
                       float* __restrict__ an, float* __restrict__ vn,
                       float* __restrict__ en){
  int row = blockIdx.x*8 + (threadIdx.x >> 5);
  int lane = threadIdx.x & 31;
  const float* x; __nv_bfloat16* xb; float* nrm; int r;
  if (row < N_){ x=a; xb=ab; nrm=an; r=row; }
  else if (row < 2*N_){ x=v; xb=vb; nrm=vn; r=row-N_; }
  else { x=e; xb=eb; nrm=en; r=row-2*N_; }
  const float4* src = (const float4*)(x + (size_t)r * D_);
  uint2* dst = (uint2*)(xb + (size_t)r * D_);
  float s = 0.f;
  #pragma unroll
  for (int i=0;i<4;i++){
    float4 f = src[lane + 32*i];
    s += f.x*f.x + f.y*f.y + f.z*f.z + f.w*f.w;
    __nv_bfloat162 h0 = __floats2bfloat162_rn(f.x, f.y);
    __nv_bfloat162 h1 = __floats2bfloat162_rn(f.z, f.w);
    uint2 o; o.x = *(unsigned*)&h0; o.y = *(unsigned*)&h1;
    dst[lane + 32*i] = o;
  }
  s = warpRedSum(s);
  if (!lane) nrm[r] = s;
}

// ---------------- HMMA machinery ----------------
__device__ __forceinline__ void cpa16(uint32_t s, const void* g){
  asm volatile("cp.async.cg.shared.global [%0], [%1], 16;" :: "r"(s), "l"(g));
}
__device__ __forceinline__ void ldmx4(uint32_t* r, uint32_t a){
  asm volatile("ldmatrix.sync.aligned.m8n8.x4.shared.b16 {%0,%1,%2,%3}, [%4];"
    : "=r"(r[0]), "=r"(r[1]), "=r"(r[2]), "=r"(r[3]) : "r"(a));
}
__device__ __forceinline__ void mma_bf16(float* c, const uint32_t* a, uint32_t b0, uint32_t b1){
  asm volatile("mma.sync.aligned.m16n8k16.row.col.f32.bf16.bf16.f32 "
    "{%0,%1,%2,%3}, {%4,%5,%6,%7}, {%8,%9}, {%0,%1,%2,%3};"
    : "+f"(c[0]), "+f"(c[1]), "+f"(c[2]), "+f"(c[3])
    : "r"(a[0]), "r"(a[1]), "r"(a[2]), "r"(a[3]), "r"(b0), "r"(b1));
}

// CTA tile 128(M) x 128(N), BK=64 (128B rows). 128 threads, 4 warps (2M x 2N),
// warp tile 64x64. NBUF=3 (96KB) -> 2 CTAs/SM. Single __syncthreads per K-chunk.
// Fragment double-buffering: ks+1 frags load overlaps ks MMAs.
#define NBUF 3
#define ABYTES 16384
#define STG 32768
#define SMEM_DYN (NBUF*STG)   // 96KB

__device__ __forceinline__ void g_load(uint32_t sbase, int st, int ck,
                                       const char* Ab, const char* Bb,
                                       long ldab, long ldbb, int tid){
  uint32_t dA = sbase + (uint32_t)st * STG;
  uint32_t dB = dA + ABYTES;
  long koff = (long)ck * 128;
  #pragma unroll
  for (int i=0;i<8;i++){
    int idx = tid + (i<<7); int r = idx >> 3, c = idx & 7;
    uint32_t off = (uint32_t)(r*128 + ((c ^ (r&7))<<4));
    cpa16(dA + off, Ab + (long)r*ldab + koff + c*16);
  }
  #pragma unroll
  for (int i=0;i<8;i++){
    int idx = tid + (i<<7); int r = idx >> 3, c = idx & 7;
    uint32_t off = (uint32_t)(r*128 + ((c ^ (r&7))<<4));
    cpa16(dB + off, Bb + (long)r*ldbb + koff + c*16);
  }
  asm volatile("cp.async.commit_group;");
}

__device__ __forceinline__ void ld_frags(uint32_t aB, uint32_t bB, int ks,
                                         int wm, int wn, int lane,
                                         uint32_t af[4][4], uint32_t bfr[4][4]){
  #pragma unroll
  for (int mi=0; mi<4; ++mi){
    int row = wm + mi*16 + (lane & 15);
    int ch  = 2*ks + (lane >> 4);
    ldmx4(af[mi], aB + (uint32_t)(row*128 + ((ch ^ (row&7))<<4)));
  }
  #pragma unroll
  for (int p=0; p<4; ++p){
    int row = wn + p*16 + ((lane>>4)<<3) + (lane&7);
    int ch  = 2*ks + ((lane>>3)&1);
    ldmx4(bfr[p], bB + (uint32_t)(row*128 + ((ch ^ (row&7))<<4)));
  }
}

template<int KT>
__device__ __forceinline__ void g_main(uint32_t sbase, const char* Ab, const char* Bb,
                                       long ldab, long ldbb,
                                       float acc[4][8][4], int tid, int lane,
                                       int wm, int wn){
  g_load(sbase, 0, 0, Ab, Bb, ldab, ldbb, tid);
  g_load(sbase, 1, 1, Ab, Bb, ldab, ldbb, tid);
  #pragma unroll 1
  for (int kt = 0; kt < KT; ++kt){
    asm volatile("cp.async.wait_group 1;");
    __syncthreads();
    if (kt+2 < KT){
      int st = (kt+2)%3;
      g_load(sbase, st, kt+2, Ab, Bb, ldab, ldbb, tid);
    } else {
      asm volatile("cp.async.commit_group;");
    }
    uint32_t aB = sbase + (uint32_t)(kt%3) * STG;
    uint32_t bB = aB + ABYTES;
    uint32_t af[2][4][4], bfr[2][4][4];
    ld_frags(aB, bB, 0, wm, wn, lane, af[0], bfr[0]);
    #pragma unroll
    for (int ks=0; ks<4; ++ks){
      int cur = ks & 1, nxt = cur ^ 1;
      if (ks < 3) ld_frags(aB, bB, ks+1, wm, wn, lane, af[nxt], bfr[nxt]);
      #pragma unroll
      for (int mi=0; mi<4; ++mi)
        #pragma unroll
        for (int ni=0; ni<8; ++ni){
          const uint32_t* bp = bfr[cur][ni>>1];
          uint32_t b0 = (ni&1) ? bp[2] : bp[0];
          uint32_t b1 = (ni&1) ? bp[3] : bp[1];
          mma_bf16(acc[mi][ni], af[cur][mi], b0, b1);
        }
    }
  }
}

// ---------------- GEMM1: sd = bf16(sqrt(max(rn+cn-2*A.E^T,0))), both modalities ----------------
__global__ void __launch_bounds__(128, 2)
k_g1(const __nv_bfloat16* __restrict__ A0, const __nv_bfloat16* __restrict__ A1,
     const __nv_bfloat16* __restrict__ E,
     __nv_bfloat16* __restrict__ C0, __nv_bfloat16* __restrict__ C1,
     const float* __restrict__ rn0, const float* __restrict__ rn1,
     const float* __restrict__ cn)
{
  extern __shared__ char dsm[];
  uint32_t sbase = (uint32_t)__cvta_generic_to_shared(dsm);
  const int tid = threadIdx.x, lane = tid & 31, warp = tid >> 5;
  const int wm = (warp & 1) * 64, wn = (warp >> 1) * 64;
  const int z = blockIdx.z;
  const __nv_bfloat16* A = z ? A1 : A0;
  const float* rn = z ? rn1 : rn0;
  __nv_bfloat16* C = z ? C1 : C0;

  const char* Ab = (const char*)A + (long)blockIdx.y * 128 * 1024;
  const char* Bb = (const char*)E + (long)blockIdx.x * 128 * 1024;

  float acc[4][8][4];
  #pragma unroll
  for (int a=0;a<4;a++)
    #pragma unroll
    for (int b=0;b<8;b++)
      #pragma unroll
      for (int c=0;c<4;c++) acc[a][b][c]=0.f;

  g_main<8>(sbase, Ab, Bb, 1024, 1024, acc, tid, lane, wm, wn);

  const int tr = lane >> 2, tc = (lane & 3) * 2;
  #pragma unroll
  for (int mi=0; mi<4; ++mi){
    int r0 = blockIdx.y*128 + wm + mi*16 + tr;
    float rn0v = rn[r0], rn1v = rn[r0+8];
    #pragma unroll
    for (int ni=0; ni<8; ++ni){
      int col = blockIdx.x*128 + wn + ni*8 + tc;
      float c0 = cn[col], c1 = cn[col+1];
      float* a = acc[mi][ni];
      __nv_bfloat162 o0 = __floats2bfloat162_rn(
          sqrtf(fmaxf(fmaf(-2.f, a[0], rn0v + c0), 0.f)),
          sqrtf(fmaxf(fmaf(-2.f, a[1], rn0v + c1), 0.f)));
      __nv_bfloat162 o1 = __floats2bfloat162_rn(
          sqrtf(fmaxf(fmaf(-2.f, a[2], rn1v + c0), 0.f)),
          sqrtf(fmaxf(fmaf(-2.f, a[3], rn1v + c1), 0.f)));
      *(__nv_bfloat162*)&C[(long)r0*M_ + col] = o0;
      *(__nv_bfloat162*)&C[(long)(r0+8)*M_ + col] = o1;
    }
  }
}

// ---------------- softmax (warp per row): adj = softmax(-2 sd), L = lse(-sd) ----------------
__global__ void __launch_bounds__(256)
k_softmax2(const __nv_bfloat16* __restrict__ sda,
           const __nv_bfloat16* __restrict__ sdv,
           __nv_bfloat16* __restrict__ adja,
           __nv_bfloat16* __restrict__ adjv,
           float* __restrict__ La, float* __restrict__ Lv){
  int rowg = blockIdx.x*8 + (threadIdx.x >> 5);
  int lane = threadIdx.x & 31;
  int which = rowg >> 14;
  int row = rowg & (N_-1);
  const __nv_bfloat16* sd = which ? sdv : sda;
  __nv_bfloat16* adj = which ? adjv : adja;
  float* L = which ? Lv : La;
  size_t base = (size_t)row * M_;
  const uint2* src = (const uint2*)(sd + base);
  uint2* dst = (uint2*)(adj + base);

  float v[32];
  float vmin = 3.4e38f;
  #pragma unroll
  for (int j=0;j<8;j++){
    uint2 pk = src[lane + 32*j];
    __nv_bfloat162 p0 = *(__nv_bfloat162*)&pk.x;
    __nv_bfloat162 p1 = *(__nv_bfloat162*)&pk.y;
    float f0 = __low2float(p0), f1 = __high2float(p0);
    float f2 = __low2float(p1), f3 = __high2float(p1);
    v[4*j]=f0; v[4*j+1]=f1; v[4*j+2]=f2; v[4*j+3]=f3;
    vmin = fminf(vmin, fminf(fminf(f0,f1), fminf(f2,f3)));
  }
  float rmin = warpRedMin(vmin);
  float s1 = 0.f, s2 = 0.f;
  #pragma unroll
  for (int k=0;k<32;k++){
    float e = __expf(rmin - v[k]);
    v[k] = e;
    s1 += e; s2 += e*e;
  }
  s1 = warpRedSum(s1);
  s2 = warpRedSum(s2);
  float i2 = 1.0f/s2;
  #pragma unroll
  for (int j=0;j<8;j++){
    float e0=v[4*j], e1=v[4*j+1], e2=v[4*j+2], e3=v[4*j+3];
    __nv_bfloat162 a0 = __floats2bfloat162_rn(e0*e0*i2, e1*e1*i2);
    __nv_bfloat162 a1 = __floats2bfloat162_rn(e2*e2*i2, e3*e3*i2);
    uint2 o; o.x = *(unsigned*)&a0; o.y = *(unsigned*)&a1;
    dst[lane + 32*j] = o;
  }
  if (!lane) L[row] = logf(s1) - rmin;
}

// ---------------- GEMM2 + fused loss epilogue ----------------
__global__ void __launch_bounds__(128, 2)
k_g2(const __nv_bfloat16* __restrict__ adjA, const __nv_bfloat16* __restrict__ adjV,
     const __nv_bfloat16* __restrict__ sdA,  const __nv_bfloat16* __restrict__ sdV,
     const float* __restrict__ La, const float* __restrict__ Lv,
     float* __restrict__ rowsum, float* __restrict__ diag)
{
  extern __shared__ char dsm[];
  uint32_t sbase = (uint32_t)__cvta_generic_to_shared(dsm);
  const int tid = threadIdx.x, lane = tid & 31, warp = tid >> 5;
  const int wm = (warp & 1) * 64, wn = (warp >> 1) * 64;
  const int pair = blockIdx.z >> 5, t = blockIdx.z & 31;
  const __nv_bfloat16* A = pair ? adjV : adjA;
  const __nv_bfloat16* Bm = pair ? sdA : sdV;
  const float* L = pair ? La : Lv;

  const char* Ab = (const char*)A + (long)t*2048 + (long)blockIdx.y * 128 * 65536;
  const char* Bb = (const char*)Bm + (long)t*2048 + (long)blockIdx.x * 128 * 65536;

  float acc[4][8][4];
  #pragma unroll
  for (int a=0;a<4;a++)
    #pragma unroll
    for (int b=0;b<8;b++)
      #pragma unroll
      for (int c=0;c<4;c++) acc[a][b][c]=0.f;

  g_main<16>(sbase, Ab, Bb, 65536, 65536, acc, tid, lane, wm, wn);

  // preload the 128 L values for this CTA's columns into smem (buffers done)
  __syncthreads();
  float* Lsm = (float*)dsm;     // 128 floats
  Lsm[tid] = L[(long)(blockIdx.x*128 + tid)*T_ + t];
  __syncthreads();

  const int tr = lane >> 2, tc = (lane & 3) * 2;
  const int batch = pair*T_ + t;
  float* dout = diag + (long)batch * B_;
  float rp[8];
  #pragma unroll
  for (int i=0;i<8;i++) rp[i]=0.f;
  #pragma unroll
  for (int mi=0; mi<4; ++mi){
    int gi0 = blockIdx.y*128 + wm + mi*16 + tr;
    #pragma unroll
    for (int ni=0; ni<8; ++ni){
      int lc = wn + ni*8 + tc;
      int gj = blockIdx.x*128 + lc;
      float L0 = Lsm[lc], L1 = Lsm[lc+1];
      float* a = acc[mi][ni];
      float p00 = __expf(-a[0]-L0), p01 = __expf(-a[1]-L1);
      float p10 = __expf(-a[2]-L0), p11 = __expf(-a[3]-L1);
      rp[mi*2]   += p00 + p01;
      rp[mi*2+1] += p10 + p11;
      if (gj   == gi0)   dout[gi0]   = p00;
      if (gj+1 == gi0)   dout[gi0]   = p01;
      if (gj   == gi0+8) dout[gi0+8] = p10;
      if (gj+1 == gi0+8) dout[gi0+8] = p11;
    }
  }
  #pragma unroll
  for (int i=0;i<8;i++){
    rp[i] += __shfl_xor_sync(0xffffffffu, rp[i], 1);
    rp[i] += __shfl_xor_sync(0xffffffffu, rp[i], 2);
  }
  __syncthreads();
  float* part = (float*)dsm + 128;         // [128][2], after Lsm
  int ng = warp >> 1;
  if ((lane & 3) == 0){
    #pragma unroll
    for (int mi=0; mi<4; ++mi){
      int r = wm + mi*16 + tr;
      part[r*2 + ng]     = rp[mi*2];
      part[(r+8)*2 + ng] = rp[mi*2+1];
    }
  }
  __syncthreads();
  {
    float s = part[tid*2] + part[tid*2+1];
    atomicAdd(&rowsum[(long)batch*B_ + blockIdx.y*128 + tid], s);
  }
}

// ---------------- loss partials and final mean ----------------
__global__ void k_loss2(const float* __restrict__ rs, const float* __restrict__ dg,
                        double* __restrict__ part){
  long base = (long)blockIdx.x * B_;
  float term = 0.f;
  #pragma unroll
  for (int h=0; h<2; ++h){
    long i = base + threadIdx.x + h*256;
    term += logf(rs[i]) - logf(dg[i]);
  }
  float s = blockSum(term);
  if (threadIdx.x == 0) part[blockIdx.x] = (double)s;
}
__global__ void k_final(const double* __restrict__ part, float* __restrict__ out){
  double s = (threadIdx.x < 64) ? part[threadIdx.x] : 0.0;
  #pragma unroll
  for (int o=16;o>0;o>>=1) s += __shfl_xor_sync(0xffffffffu, s, o);
  __shared__ double sm[2];
  if ((threadIdx.x & 31) == 0) sm[threadIdx.x>>5] = s;
  __syncthreads();
  if (threadIdx.x == 0) out[0] = (float)((sm[0]+sm[1]) / 32768.0);
}

// ---------------- launch ----------------
extern "C" void kernel_launch(void* const* d_in, const int* in_sizes, int n_in,
                              void* d_out, int out_size)
{
  const float* a = (const float*)d_in[0];
  const float* v = (const float*)d_in[1];
  const float* e = (const float*)d_in[2];
  float* out = (float*)d_out;

  __nv_bfloat16 *pa, *pv, *pe, *psa, *psv, *paa, *pav;
  float *pan, *pvn, *pen, *pLa, *pLv, *prs, *pdg;
  double *ppt;
  cudaGetSymbolAddress((void**)&pa,  g_a_bf);
  cudaGetSymbolAddress((void**)&pv,  g_v_bf);
  cudaGetSymbolAddress((void**)&pe,  g_e_bf);
  cudaGetSymbolAddress((void**)&pan, g_an);
  cudaGetSymbolAddress((void**)&pvn, g_vn);
  cudaGetSymbolAddress((void**)&pen, g_en);
  cudaGetSymbolAddress((void**)&psa, g_sd_a);
  cudaGetSymbolAddress((void**)&psv, g_sd_v);
  cudaGetSymbolAddress((void**)&paa, g_adj_a);
  cudaGetSymbolAddress((void**)&pav, g_adj_v);
  cudaGetSymbolAddress((void**)&pLa, g_L_a);
  cudaGetSymbolAddress((void**)&pLv, g_L_v);
  cudaGetSymbolAddress((void**)&prs, g_rowsum);
  cudaGetSymbolAddress((void**)&pdg, g_diag);
  cudaGetSymbolAddress((void**)&ppt, g_part);

  cudaFuncSetAttribute(k_g1, cudaFuncAttributeMaxDynamicSharedMemorySize, SMEM_DYN);
  cudaFuncSetAttribute(k_g2, cudaFuncAttributeMaxDynamicSharedMemorySize, SMEM_DYN);

  k_zero<<<64, 512>>>(prs);
  k_prep<<<(2*N_+M_)/8, 256>>>(a, v, e, pa, pv, pe, pan, pvn, pen);

  dim3 g1(M_/128, N_/128, 2);
  k_g1<<<g1, 128, SMEM_DYN>>>(pa, pv, pe, psa, psv, pan, pvn, pen);

  k_softmax2<<<2*N_/8, 256>>>(psa, psv, paa, pav, pLa, pLv);

  dim3 g2(B_/128, B_/128, 64);
  k_g2<<<g2, 128, SMEM_DYN>>>(paa, pav, psa, psv, pLa, pLv, prs, pdg);

  k_loss2<<<64, 256>>>(prs, pdg, ppt);
  k_final<<<1, 64>>>(ppt, out);
}